// round 14
// baseline (speedup 1.0000x reference)
#include <cuda_runtime.h>
#include <cuda_fp16.h>
#include <cstdint>

// Problem constants
#define BATCH   2
#define SEQ     2048
#define DIMM    1024
#define NHEAD   16
#define HDIM    64

#define GM 4096
#define GN 1024
#define GK 1024

#define QSCALE (0.125f * 1.44269504088896f)   // 1/sqrt(64) * log2(e)

// ---------------- scratch (allocation-free: device globals) ----------------
// tf32 pair-packed operands: AP[m][pc] = (x[m][8g+tq], x[m][8g+tq+4]), pc=4g+tq
static __device__ float2 g_apq[GM * (GK / 2)];
static __device__ float2 g_apk[GM * (GK / 2)];
static __device__ float2 g_apv[GM * (GK / 2)];
static __device__ float2 g_aop[GM * (GK / 2)];
// BP[pc][n] = (W[k1][n], W[k2][n]) with k1=8g+tq, k2=k1+4
static __device__ float2 g_bpq[(GK / 2) * GN];
static __device__ float2 g_bpk[(GK / 2) * GN];
static __device__ float2 g_bpv[(GK / 2) * GN];
static __device__ float2 g_bpo[(GK / 2) * GN];
// fp16 attention operands, [B,H,S,hd], written by projection GEMM epilogue
static __device__ __half g_q16h[BATCH * NHEAD * SEQ * HDIM];
static __device__ __half g_q16l[BATCH * NHEAD * SEQ * HDIM];
static __device__ __half g_k16h[BATCH * NHEAD * SEQ * HDIM];
static __device__ __half g_k16l[BATCH * NHEAD * SEQ * HDIM];
static __device__ __half g_v16 [BATCH * NHEAD * SEQ * HDIM];

// ---------------- helpers -----------------------------------------------------
__device__ __forceinline__ unsigned f2tf32(float x) {
    unsigned r;
    asm("cvt.rna.tf32.f32 %0, %1;" : "=r"(r) : "f"(x));
    return r;
}
__device__ __forceinline__ float tfr(float x) {          // tf32-rounded float
    return __uint_as_float(f2tf32(x));
}
__device__ __forceinline__ float ex2(float x) {
    float y;
    asm("ex2.approx.ftz.f32 %0, %1;" : "=f"(y) : "f"(x));
    return y;
}
__device__ __forceinline__ void cp16s(uint32_t smem_dst, const void* gmem_src) {
    asm volatile("cp.async.cg.shared.global [%0], [%1], 16;"
                 :: "r"(smem_dst), "l"(gmem_src));
}

// ---------------- combined preconvert kernel ---------------------------------
// y = 0..2: inputs q/k/v -> AP pair layout (2048 blocks used)
// y = 3..6: weights -> BP pair layout (1024 blocks used)
__global__ __launch_bounds__(256)
void cvt_all_kernel(const float* __restrict__ q, const float* __restrict__ k,
                    const float* __restrict__ v,
                    const float* __restrict__ Wq, const float* __restrict__ Wk,
                    const float* __restrict__ Wv, const float* __restrict__ Wo)
{
    const int y = blockIdx.y;
    if (y < 3) {
        const float* s = (y == 0) ? q : (y == 1) ? k : v;
        float2* d = (y == 0) ? g_apq : (y == 1) ? g_apk : g_apv;
        int flat = blockIdx.x * 256 + threadIdx.x;
        int m  = flat >> 7;
        int g8 = flat & 127;
        const float* row = s + (size_t)m * GK + g8 * 8;
        float4 a = *(const float4*)row;
        float4 b = *(const float4*)(row + 4);
        float2* o = d + (size_t)m * (GK / 2) + g8 * 4;
        o[0] = make_float2(tfr(a.x), tfr(b.x));
        o[1] = make_float2(tfr(a.y), tfr(b.y));
        o[2] = make_float2(tfr(a.z), tfr(b.z));
        o[3] = make_float2(tfr(a.w), tfr(b.w));
    } else {
        if (blockIdx.x >= 1024) return;
        const int w = y - 3;
        const float* W = (w == 0) ? Wq : (w == 1) ? Wk : (w == 2) ? Wv : Wo;
        float2* o = (w == 0) ? g_bpq : (w == 1) ? g_bpk : (w == 2) ? g_bpv : g_bpo;
        int flat = blockIdx.x * 256 + threadIdx.x;
        int pc = flat >> 9;
        int n2 = (flat & 511) * 2;
        int g8 = pc >> 2, tq = pc & 3;
        int k1 = 8 * g8 + tq, k2 = k1 + 4;
#pragma unroll
        for (int j = 0; j < 2; j++) {
            int n = n2 + j;
            float v1, v2;
            if (w < 3) {
                int hh = n >> 6, e = n & 63;
                v1 = W[((size_t)hh * GK + k1) * 64 + e];
                v2 = W[((size_t)hh * GK + k2) * 64 + e];
            } else {
                v1 = W[(size_t)k1 * GN + n];
                v2 = W[(size_t)k2 * GN + n];
            }
            o[(size_t)pc * GN + n] = make_float2(tfr(v1), tfr(v2));
        }
    }
}

// ---- pair-packed tf32 GEMM: 128x128, 3-stage smem, 2-stage reg frags -------
// MODE 0: projection; z selects q/k/v; epilogue -> fp16 hi/lo [B,H,S,hd]
// MODE 1: plain GEMM -> f32 C.
#define BM 128
#define BN 128
#define BKK 32
#define AROW 160                       // A bytes/row: 128 data + 32 pad
#define BROW 1056                      // B bytes/row: 1024 data + 32 pad
#define ATILE (BM * AROW)              // 20480
#define STAGEB (ATILE + 16 * BROW)     // 37376
#define GSTAGES 3
#define GEMM_SMEM (GSTAGES * STAGEB)   // 112128

template <int MODE>
__global__ __launch_bounds__(256, 2)
void gemm_kernel(const float2* __restrict__ A0, const float2* __restrict__ A1,
                 const float2* __restrict__ A2,
                 const float2* __restrict__ B0, const float2* __restrict__ B1,
                 const float2* __restrict__ B2,
                 __half* __restrict__ H0, __half* __restrict__ L0,
                 __half* __restrict__ H1, __half* __restrict__ L1,
                 __half* __restrict__ H2,
                 float* __restrict__ C)
{
    extern __shared__ char smraw[];
    const uint32_t smU = (uint32_t)__cvta_generic_to_shared(smraw);

    const int z = blockIdx.z;
    const float2* A = (z == 0) ? A0 : (z == 1) ? A1 : A2;
    const float2* B = (z == 0) ? B0 : (z == 1) ? B1 : B2;

    const int tid  = threadIdx.x;
    const int m0   = blockIdx.x * BM;
    const int n0   = blockIdx.y * BN;
    const int warp = tid >> 5;
    const int lane = tid & 31;
    const int warpM = warp & 1;          // 64-row halves
    const int warpN = warp >> 1;         // 32-col quarters
    const int g  = lane >> 2;
    const int tq = lane & 3;
    const int m0w = warpM * 64;
    const int n0w = warpN * 32;

    float acc[4][4][4];
#pragma unroll
    for (int i = 0; i < 4; i++)
#pragma unroll
        for (int j = 0; j < 4; j++)
#pragma unroll
            for (int r = 0; r < 4; r++) acc[i][j][r] = 0.f;

    auto load_tile = [&](int it, int s) {
        const int pc0 = it * 16;
        const uint32_t sb = smU + (uint32_t)s * STAGEB;
#pragma unroll
        for (int p = 0; p < 4; p++) {          // A: 1024 16B chunks
            int slot = tid + p * 256;
            int r = slot >> 3;
            int c = slot & 7;
            cp16s(sb + (uint32_t)(r * AROW + c * 16),
                  A + (size_t)(m0 + r) * (GK / 2) + pc0 + c * 2);
        }
#pragma unroll
        for (int p = 0; p < 4; p++) {          // B: 1024 16B chunks
            int slot = tid + p * 256;
            int r = slot >> 6;
            int c = slot & 63;
            cp16s(sb + (uint32_t)(ATILE + r * BROW + c * 16),
                  B + (size_t)(pc0 + r) * GN + n0 + c * 2);
        }
        asm volatile("cp.async.commit_group;");
    };

    const int NIT = GK / BKK;   // 32
    load_tile(0, 0);
    load_tile(1, 1);

    // register fragment double buffers
    float2 aL[2][4], aH[2][4], bF[2][4];

    int sidx = 0;
    for (int it = 0; it < NIT; it++) {
        if (it + 1 < NIT) {
            asm volatile("cp.async.wait_group 1;");   // tile it landed
        } else {
            asm volatile("cp.async.wait_group 0;");
        }
        __syncthreads();   // tile it visible; compute(it-1) done

        if (it + 2 < NIT) {
            int sl = sidx + 2; if (sl >= GSTAGES) sl -= GSTAGES;
            load_tile(it + 2, sl);
        }

        const char* sb = smraw + sidx * STAGEB;

        // ---- load ks=0 fragments into buffer 0
        {
            const int pr = tq;
#pragma unroll
            for (int nf = 0; nf < 4; nf++)
                bF[0][nf] = *(const float2*)(sb + ATILE + pr * BROW
                                             + (n0w + nf * 8 + g) * 8);
#pragma unroll
            for (int mf = 0; mf < 4; mf++) {
                const char* ar = sb + (m0w + mf * 16 + g) * AROW + pr * 8;
                aL[0][mf] = *(const float2*)ar;
                aH[0][mf] = *(const float2*)(ar + 8 * AROW);
            }
        }

#pragma unroll
        for (int ks = 0; ks < 4; ks++) {
            const int cur = ks & 1, nxt = cur ^ 1;
            // prefetch ks+1 fragments into the other buffer
            if (ks < 3) {
                const int pr = 4 * (ks + 1) + tq;
#pragma unroll
                for (int nf = 0; nf < 4; nf++)
                    bF[nxt][nf] = *(const float2*)(sb + ATILE + pr * BROW
                                                   + (n0w + nf * 8 + g) * 8);
#pragma unroll
                for (int mf = 0; mf < 4; mf++) {
                    const char* ar = sb + (m0w + mf * 16 + g) * AROW + pr * 8;
                    aL[nxt][mf] = *(const float2*)ar;
                    aH[nxt][mf] = *(const float2*)(ar + 8 * AROW);
                }
            }
            // compute with current buffer
#pragma unroll
            for (int mf = 0; mf < 4; mf++)
#pragma unroll
                for (int nf = 0; nf < 4; nf++) {
                    asm volatile(
                        "mma.sync.aligned.m16n8k8.row.col.f32.tf32.tf32.f32 "
                        "{%0,%1,%2,%3}, {%4,%5,%6,%7}, {%8,%9}, {%0,%1,%2,%3};"
                        : "+f"(acc[mf][nf][0]), "+f"(acc[mf][nf][1]),
                          "+f"(acc[mf][nf][2]), "+f"(acc[mf][nf][3])
                        : "r"(__float_as_uint(aL[cur][mf].x)),
                          "r"(__float_as_uint(aH[cur][mf].x)),
                          "r"(__float_as_uint(aL[cur][mf].y)),
                          "r"(__float_as_uint(aH[cur][mf].y)),
                          "r"(__float_as_uint(bF[cur][nf].x)),
                          "r"(__float_as_uint(bF[cur][nf].y)));
                }
        }
        sidx = sidx + 1; if (sidx >= GSTAGES) sidx -= GSTAGES;
    }

    // ---- epilogue
    const float scl = (MODE == 0 && z == 0) ? QSCALE : 1.f;
    __half* OH = (z == 0) ? H0 : (z == 1) ? H1 : H2;
    __half* OL = (z == 0) ? L0 : L1;                 // unused for z==2
#pragma unroll
    for (int mf = 0; mf < 4; mf++) {
#pragma unroll
        for (int nf = 0; nf < 4; nf++) {
            const int gcol = n0 + n0w + nf * 8 + 2 * tq;
#pragma unroll
            for (int half = 0; half < 2; half++) {
                const int grow = m0 + m0w + mf * 16 + g + half * 8;
                float x0 = acc[mf][nf][half * 2]     * scl;
                float x1 = acc[mf][nf][half * 2 + 1] * scl;
                if (MODE == 0) {
                    const int bb = grow >> 11, ss = grow & 2047;
                    const int hh = gcol >> 6, e = gcol & 63;
                    const size_t idx =
                        (((size_t)(bb * NHEAD + hh)) * SEQ + ss) * HDIM + e;
                    __half h0 = __float2half_rn(x0);
                    __half h1 = __float2half_rn(x1);
                    __half2 hv; hv.x = h0; hv.y = h1;
                    *(__half2*)(OH + idx) = hv;
                    if (z < 2) {
                        __half l0 = __float2half_rn(x0 - __half2float(h0));
                        __half l1 = __float2half_rn(x1 - __half2float(h1));
                        __half2 lv; lv.x = l0; lv.y = l1;
                        *(__half2*)(OL + idx) = lv;
                    }
                } else {
                    *(float2*)(C + (size_t)grow * GN + gcol) =
                        make_float2(x0, x1);
                }
            }
        }
    }
}

// ================= MMA flash attention (R11, unchanged) =====================
#define TQA 128
#define TKA 64

#define OFF_QHI 0
#define OFF_QLO 18432
#define OFF_STG 36864
#define STG_B   27648     // Khi 9216 + Klo 9216 + V 9216
#define OFF_QM  92160
#define OFF_KM  92672
#define ATTN_SMEM 93696

#define MMA16816(CC, A0, A1, A2, A3, B0, B1)                                  \
    asm volatile(                                                             \
        "mma.sync.aligned.m16n8k16.row.col.f32.f16.f16.f32 "                  \
        "{%0,%1,%2,%3}, {%4,%5,%6,%7}, {%8,%9}, {%0,%1,%2,%3};"               \
        : "+f"((CC)[0]), "+f"((CC)[1]), "+f"((CC)[2]), "+f"((CC)[3])          \
        : "r"(A0), "r"(A1), "r"(A2), "r"(A3), "r"(B0), "r"(B1))

#define LDSM_X4(R0, R1, R2, R3, ADDR)                                         \
    asm volatile("ldmatrix.sync.aligned.m8n8.x4.shared.b16 {%0,%1,%2,%3}, [%4];" \
                 : "=r"(R0), "=r"(R1), "=r"(R2), "=r"(R3) : "r"(ADDR))

#define LDSM_X4T(R0, R1, R2, R3, ADDR)                                        \
    asm volatile("ldmatrix.sync.aligned.m8n8.x4.trans.shared.b16 {%0,%1,%2,%3}, [%4];" \
                 : "=r"(R0), "=r"(R1), "=r"(R2), "=r"(R3) : "r"(ADDR))

__device__ __forceinline__ uint32_t pack_h2(float a, float b) {
    __half2 h = __floats2half2_rn(a, b);
    return *(uint32_t*)&h;
}

__global__ __launch_bounds__(256, 2)
void attn_mma_kernel(const __half* __restrict__ QHI, const __half* __restrict__ QLO,
                     const __half* __restrict__ KHI, const __half* __restrict__ KLO,
                     const __half* __restrict__ V16, const int* __restrict__ mask,
                     float2* __restrict__ AOP)
{
    extern __shared__ char smem_raw[];
    const uint32_t smU = (uint32_t)__cvta_generic_to_shared(smem_raw);

    const int b = blockIdx.z, h = blockIdx.y;
    const int qt = (int)gridDim.x - 1 - (int)blockIdx.x;   // heavy tiles first
    const int q0 = qt * TQA;
    const size_t base = ((size_t)(b * NHEAD + h)) * SEQ * HDIM;
    const int mrow = b * SEQ;

    const int tid  = threadIdx.x;
    const int warp = tid >> 5, lane = tid & 31;
    const int g = lane >> 2, t = lane & 3;

    auto load_tile = [&](int t0n, int s) {
        const uint32_t sb = smU + OFF_STG + (uint32_t)s * STG_B;
#pragma unroll
        for (int p = 0; p < 6; p++) {
            int slot = tid + p * 256;
            int arr  = slot >> 9;                // 0=Khi 1=Klo 2=V
            int rem  = slot & 511;
            int r    = rem >> 3;
            int cB   = (rem & 7) * 16;
            const __half* src = (arr == 0) ? KHI : (arr == 1) ? KLO : V16;
            cp16s(sb + (uint32_t)(arr * 9216 + r * 144 + cB),
                  src + base + (size_t)(t0n + r) * HDIM + (cB >> 1));
        }
        if (tid < 16)
            cp16s(smU + OFF_KM + (uint32_t)(s * 256 + tid * 16),
                  mask + mrow + t0n + tid * 4);
        asm volatile("cp.async.commit_group;");
    };

    {
#pragma unroll
        for (int p = 0; p < 8; p++) {
            int slot = tid + p * 256;
            int arr  = slot >> 10;               // 0=Qhi 1=Qlo
            int rem  = slot & 1023;
            int r    = rem >> 3;
            int cB   = (rem & 7) * 16;
            const __half* src = arr ? QLO : QHI;
            cp16s(smU + (arr ? OFF_QLO : OFF_QHI) + (uint32_t)(r * 144 + cB),
                  src + base + (size_t)(q0 + r) * HDIM + (cB >> 1));
        }
        if (tid < 32)
            cp16s(smU + OFF_QM + (uint32_t)(tid * 16), mask + mrow + q0 + tid * 4);
    }
    load_tile(0, 0);

    const int r0l = warp * 16 + g;
    const int r1l = r0l + 8;
    const int srow0 = q0 + r0l, srow1 = q0 + r1l;

    const float NEGINF = __int_as_float(0xff800000u);
    float m0 = NEGINF, m1 = NEGINF, l0 = 0.f, l1 = 0.f;
    float acc[8][4];
#pragma unroll
    for (int i = 0; i < 8; i++)
#pragma unroll
        for (int j = 0; j < 4; j++) acc[i][j] = 0.f;

    const uint32_t qoff = (uint32_t)((warp * 16 + (lane & 15)) * 144
                                     + (lane >> 4) * 16);
    const uint32_t koff = (uint32_t)((((lane >> 4) * 8) + (lane & 7)) * 144
                                     + ((lane >> 3) & 1) * 16);
    const uint32_t voff = (uint32_t)((lane & 15) * 144 + (lane >> 4) * 16);
    const uint32_t qhiB = smU + OFF_QHI + qoff;
    const uint32_t qloB = smU + OFF_QLO + qoff;

    const int* qm = (const int*)(smem_raw + OFF_QM);

    const int ntiles = (q0 + TQA) / TKA;
    for (int kt = 0; kt < ntiles; kt++) {
        const int t0 = kt * TKA;
        asm volatile("cp.async.wait_group 0;");
        __syncthreads();

        if (kt + 1 < ntiles) load_tile(t0 + TKA, (kt + 1) & 1);

        const uint32_t stb  = smU + OFF_STG + (uint32_t)(kt & 1) * STG_B;
        const uint32_t khiB = stb + koff;
        const uint32_t kloB = stb + 9216 + koff;
        const uint32_t vB   = stb + 18432 + voff;
        const int* km = (const int*)(smem_raw + OFF_KM + (kt & 1) * 256);

        float sc[8][4];
#pragma unroll
        for (int i = 0; i < 8; i++)
#pragma unroll
            for (int j = 0; j < 4; j++) sc[i][j] = 0.f;

#pragma unroll
        for (int kj = 0; kj < 4; kj++) {
            uint32_t ah0, ah1, ah2, ah3, al0, al1, al2, al3;
            LDSM_X4(ah0, ah1, ah2, ah3, qhiB + kj * 32);
            LDSM_X4(al0, al1, al2, al3, qloB + kj * 32);
#pragma unroll
            for (int nfp = 0; nfp < 4; nfp++) {
                const uint32_t kk = (uint32_t)(nfp * 16 * 144 + kj * 32);
                uint32_t bh0, bh1, bh2, bh3, bl0, bl1, bl2, bl3;
                LDSM_X4(bh0, bh1, bh2, bh3, khiB + kk);
                LDSM_X4(bl0, bl1, bl2, bl3, kloB + kk);
                MMA16816(sc[2 * nfp],     ah0, ah1, ah2, ah3, bh0, bh1);
                MMA16816(sc[2 * nfp],     ah0, ah1, ah2, ah3, bl0, bl1);
                MMA16816(sc[2 * nfp],     al0, al1, al2, al3, bh0, bh1);
                MMA16816(sc[2 * nfp + 1], ah0, ah1, ah2, ah3, bh2, bh3);
                MMA16816(sc[2 * nfp + 1], ah0, ah1, ah2, ah3, bl2, bl3);
                MMA16816(sc[2 * nfp + 1], al0, al1, al2, al3, bh2, bh3);
            }
        }

        const bool rm0 = (qm[r0l] != 0), rm1 = (qm[r1l] != 0);
        float mx0 = m0, mx1 = m1;
        if (t0 + TKA > q0) {
#pragma unroll
            for (int nf = 0; nf < 8; nf++) {
                const int c0i = nf * 8 + 2 * t, c1i = c0i + 1;
                const bool cm0 = (km[c0i] != 0), cm1 = (km[c1i] != 0);
                const int tc0 = t0 + c0i, tc1 = t0 + c1i;
                float v00 = (rm0 | cm0) ? 0.f : sc[nf][0]; if (tc0 > srow0) v00 = -1e30f;
                float v01 = (rm0 | cm1) ? 0.f : sc[nf][1]; if (tc1 > srow0) v01 = -1e30f;
                float v10 = (rm1 | cm0) ? 0.f : sc[nf][2]; if (tc0 > srow1) v10 = -1e30f;
                float v11 = (rm1 | cm1) ? 0.f : sc[nf][3]; if (tc1 > srow1) v11 = -1e30f;
                sc[nf][0] = v00; sc[nf][1] = v01; sc[nf][2] = v10; sc[nf][3] = v11;
                mx0 = fmaxf(mx0, fmaxf(v00, v01));
                mx1 = fmaxf(mx1, fmaxf(v10, v11));
            }
        } else {
#pragma unroll
            for (int nf = 0; nf < 8; nf++) {
                const int c0i = nf * 8 + 2 * t, c1i = c0i + 1;
                const bool cm0 = (km[c0i] != 0), cm1 = (km[c1i] != 0);
                float v00 = (rm0 | cm0) ? 0.f : sc[nf][0];
                float v01 = (rm0 | cm1) ? 0.f : sc[nf][1];
                float v10 = (rm1 | cm0) ? 0.f : sc[nf][2];
                float v11 = (rm1 | cm1) ? 0.f : sc[nf][3];
                sc[nf][0] = v00; sc[nf][1] = v01; sc[nf][2] = v10; sc[nf][3] = v11;
                mx0 = fmaxf(mx0, fmaxf(v00, v01));
                mx1 = fmaxf(mx1, fmaxf(v10, v11));
            }
        }
#pragma unroll
        for (int off = 1; off <= 2; off <<= 1) {
            mx0 = fmaxf(mx0, __shfl_xor_sync(0xffffffffu, mx0, off));
            mx1 = fmaxf(mx1, __shfl_xor_sync(0xffffffffu, mx1, off));
        }
        const float corr0 = ex2(m0 - mx0);
        const float corr1 = ex2(m1 - mx1);
        float rs0 = 0.f, rs1 = 0.f;
#pragma unroll
        for (int nf = 0; nf < 8; nf++) {
            float p00 = ex2(sc[nf][0] - mx0);
            float p01 = ex2(sc[nf][1] - mx0);
            float p10 = ex2(sc[nf][2] - mx1);
            float p11 = ex2(sc[nf][3] - mx1);
            sc[nf][0] = p00; sc[nf][1] = p01; sc[nf][2] = p10; sc[nf][3] = p11;
            rs0 += p00 + p01;
            rs1 += p10 + p11;
        }
#pragma unroll
        for (int off = 1; off <= 2; off <<= 1) {
            rs0 += __shfl_xor_sync(0xffffffffu, rs0, off);
            rs1 += __shfl_xor_sync(0xffffffffu, rs1, off);
        }
        l0 = l0 * corr0 + rs0;  m0 = mx0;
        l1 = l1 * corr1 + rs1;  m1 = mx1;
#pragma unroll
        for (int nfd = 0; nfd < 8; nfd++) {
            acc[nfd][0] *= corr0; acc[nfd][1] *= corr0;
            acc[nfd][2] *= corr1; acc[nfd][3] *= corr1;
        }

#pragma unroll
        for (int kj = 0; kj < 4; kj++) {
            uint32_t a0 = pack_h2(sc[2 * kj][0],     sc[2 * kj][1]);
            uint32_t a1 = pack_h2(sc[2 * kj][2],     sc[2 * kj][3]);
            uint32_t a2 = pack_h2(sc[2 * kj + 1][0], sc[2 * kj + 1][1]);
            uint32_t a3 = pack_h2(sc[2 * kj + 1][2], sc[2 * kj + 1][3]);
            const uint32_t vrow = vB + (uint32_t)(kj * 16 * 144);
#pragma unroll
            for (int p = 0; p < 4; p++) {
                uint32_t b0, b1, b2, b3;
                LDSM_X4T(b0, b1, b2, b3, vrow + (uint32_t)(p * 32));
                MMA16816(acc[2 * p],     a0, a1, a2, a3, b0, b1);
                MMA16816(acc[2 * p + 1], a0, a1, a2, a3, b2, b3);
            }
        }
    }

    // ---- epilogue: normalize + tf32-round, write pair layout for Wo GEMM
    const float inv0 = 1.f / l0, inv1 = 1.f / l1;
    float* AO = (float*)AOP;
#pragma unroll
    for (int nfd = 0; nfd < 8; nfd++) {
        const int pcb  = 4 * nfd + ((2 * t) & 3);
        const int comp = t >> 1;
        const size_t i00 = ((base + (size_t)srow0 * HDIM) + pcb * 2) + comp;
        const size_t i10 = ((base + (size_t)srow1 * HDIM) + pcb * 2) + comp;
        AO[i00]     = tfr(acc[nfd][0] * inv0);
        AO[i00 + 2] = tfr(acc[nfd][1] * inv0);
        AO[i10]     = tfr(acc[nfd][2] * inv1);
        AO[i10 + 2] = tfr(acc[nfd][3] * inv1);
    }
}

// ---------------- launch -----------------------------------------------------
extern "C" void kernel_launch(void* const* d_in, const int* in_sizes, int n_in,
                              void* d_out, int out_size)
{
    const float* q    = (const float*)d_in[0];
    const float* k    = (const float*)d_in[1];
    const float* v    = (const float*)d_in[2];
    const float* Wq   = (const float*)d_in[3];
    const float* Wk   = (const float*)d_in[4];
    const float* Wv   = (const float*)d_in[5];
    const float* Wo   = (const float*)d_in[6];
    const int*   mask = (const int*)d_in[7];
    float* out = (float*)d_out;

    float2 *apq, *apk, *apv, *aop, *bpq, *bpk, *bpv, *bpo;
    __half *q16h, *q16l, *k16h, *k16l, *v16;
    cudaGetSymbolAddress((void**)&apq, g_apq);
    cudaGetSymbolAddress((void**)&apk, g_apk);
    cudaGetSymbolAddress((void**)&apv, g_apv);
    cudaGetSymbolAddress((void**)&aop, g_aop);
    cudaGetSymbolAddress((void**)&bpq, g_bpq);
    cudaGetSymbolAddress((void**)&bpk, g_bpk);
    cudaGetSymbolAddress((void**)&bpv, g_bpv);
    cudaGetSymbolAddress((void**)&bpo, g_bpo);
    cudaGetSymbolAddress((void**)&q16h, g_q16h);
    cudaGetSymbolAddress((void**)&q16l, g_q16l);
    cudaGetSymbolAddress((void**)&k16h, g_k16h);
    cudaGetSymbolAddress((void**)&k16l, g_k16l);
    cudaGetSymbolAddress((void**)&v16,  g_v16);

    // combined preconvert: y 0..2 inputs (2048 blocks), y 3..6 weights (1024)
    dim3 gcv(2048, 7);
    cvt_all_kernel<<<gcv, 256>>>(q, k, v, Wq, Wk, Wv, Wo);

    cudaFuncSetAttribute(gemm_kernel<0>,
                         cudaFuncAttributeMaxDynamicSharedMemorySize, GEMM_SMEM);
    cudaFuncSetAttribute(gemm_kernel<1>,
                         cudaFuncAttributeMaxDynamicSharedMemorySize, GEMM_SMEM);

    // fused q/k/v projections -> fp16 hi/lo attention operands
    dim3 gp(GM / BM, GN / BN, 3);   // 32 x 8 x 3
    gemm_kernel<0><<<gp, 256, GEMM_SMEM>>>(apq, apk, apv, bpq, bpk, bpv,
                                           q16h, q16l, k16h, k16l, v16,
                                           nullptr);

    cudaFuncSetAttribute(attn_mma_kernel,
                         cudaFuncAttributeMaxDynamicSharedMemorySize, ATTN_SMEM);
    dim3 ga(SEQ / TQA, NHEAD, BATCH);   // 16 x 16 x 2
    attn_mma_kernel<<<ga, 256, ATTN_SMEM>>>(q16h, q16l, k16h, k16l, v16,
                                            mask, aop);

    // output projection: aop already tf32-rounded pair layout
    dim3 go(GM / BM, GN / BN, 1);   // 32 x 8
    gemm_kernel<1><<<go, 256, GEMM_SMEM>>>(aop, aop, aop, bpo, bpo, bpo,
                                           nullptr, nullptr, nullptr, nullptr,
                                           nullptr, out);
}

// round 15
// speedup vs baseline: 1.0477x; 1.0477x over previous
#include <cuda_runtime.h>
#include <cuda_fp16.h>
#include <cstdint>

// Problem constants
#define BATCH   2
#define SEQ     2048
#define DIMM    1024
#define NHEAD   16
#define HDIM    64

#define GM 4096
#define GN 1024
#define GK 1024

#define QSCALE (0.125f * 1.44269504088896f)   // 1/sqrt(64) * log2(e)

// ---------------- scratch (allocation-free: device globals) ----------------
// tf32 pair-packed operands: AP[m][pc] = (x[m][8g+tq], x[m][8g+tq+4]), pc=4g+tq
static __device__ float2 g_apq[GM * (GK / 2)];
static __device__ float2 g_apk[GM * (GK / 2)];
static __device__ float2 g_apv[GM * (GK / 2)];
static __device__ float2 g_aop[GM * (GK / 2)];
// BP[pc][n] = (W[k1][n], W[k2][n]) with k1=8g+tq, k2=k1+4
static __device__ float2 g_bpq[(GK / 2) * GN];
static __device__ float2 g_bpk[(GK / 2) * GN];
static __device__ float2 g_bpv[(GK / 2) * GN];
static __device__ float2 g_bpo[(GK / 2) * GN];
// fp16 attention operands, [B,H,S,hd], written by projection GEMM epilogue
static __device__ __half g_q16h[BATCH * NHEAD * SEQ * HDIM];
static __device__ __half g_q16l[BATCH * NHEAD * SEQ * HDIM];
static __device__ __half g_k16h[BATCH * NHEAD * SEQ * HDIM];
static __device__ __half g_k16l[BATCH * NHEAD * SEQ * HDIM];
static __device__ __half g_v16 [BATCH * NHEAD * SEQ * HDIM];

// ---------------- helpers -----------------------------------------------------
__device__ __forceinline__ unsigned f2tf32(float x) {
    unsigned r;
    asm("cvt.rna.tf32.f32 %0, %1;" : "=r"(r) : "f"(x));
    return r;
}
__device__ __forceinline__ float tfr(float x) {          // tf32-rounded float
    return __uint_as_float(f2tf32(x));
}
__device__ __forceinline__ float ex2(float x) {
    float y;
    asm("ex2.approx.ftz.f32 %0, %1;" : "=f"(y) : "f"(x));
    return y;
}
__device__ __forceinline__ void cp16s(uint32_t smem_dst, const void* gmem_src) {
    asm volatile("cp.async.cg.shared.global [%0], [%1], 16;"
                 :: "r"(smem_dst), "l"(gmem_src));
}

// ---------------- combined preconvert kernel ---------------------------------
// y = 0..2: inputs q/k/v -> AP pair layout (2048 blocks used)
// y = 3..6: weights -> BP pair layout (first 1024 blocks used)
__global__ __launch_bounds__(256)
void cvt_all_kernel(const float* __restrict__ q, const float* __restrict__ k,
                    const float* __restrict__ v,
                    const float* __restrict__ Wq, const float* __restrict__ Wk,
                    const float* __restrict__ Wv, const float* __restrict__ Wo)
{
    const int y = blockIdx.y;
    if (y < 3) {
        const float* s = (y == 0) ? q : (y == 1) ? k : v;
        float2* d = (y == 0) ? g_apq : (y == 1) ? g_apk : g_apv;
        int flat = blockIdx.x * 256 + threadIdx.x;
        int m  = flat >> 7;
        int g8 = flat & 127;
        const float* row = s + (size_t)m * GK + g8 * 8;
        float4 a = *(const float4*)row;
        float4 b = *(const float4*)(row + 4);
        float2* o = d + (size_t)m * (GK / 2) + g8 * 4;
        o[0] = make_float2(tfr(a.x), tfr(b.x));
        o[1] = make_float2(tfr(a.y), tfr(b.y));
        o[2] = make_float2(tfr(a.z), tfr(b.z));
        o[3] = make_float2(tfr(a.w), tfr(b.w));
    } else {
        if (blockIdx.x >= 1024) return;
        const int w = y - 3;
        const float* W = (w == 0) ? Wq : (w == 1) ? Wk : (w == 2) ? Wv : Wo;
        float2* o = (w == 0) ? g_bpq : (w == 1) ? g_bpk : (w == 2) ? g_bpv : g_bpo;
        int flat = blockIdx.x * 256 + threadIdx.x;
        int pc = flat >> 9;
        int n2 = (flat & 511) * 2;
        int g8 = pc >> 2, tq = pc & 3;
        int k1 = 8 * g8 + tq, k2 = k1 + 4;
#pragma unroll
        for (int j = 0; j < 2; j++) {
            int n = n2 + j;
            float v1, v2;
            if (w < 3) {
                int hh = n >> 6, e = n & 63;
                v1 = W[((size_t)hh * GK + k1) * 64 + e];
                v2 = W[((size_t)hh * GK + k2) * 64 + e];
            } else {
                v1 = W[(size_t)k1 * GN + n];
                v2 = W[(size_t)k2 * GN + n];
            }
            o[(size_t)pc * GN + n] = make_float2(tfr(v1), tfr(v2));
        }
    }
}

// ---- pair-packed tf32 GEMM: 128x128 tile, 3-stage, 1 barrier/iter (R13) ----
// MODE 0: projection; z selects q/k/v; epilogue -> fp16 hi/lo [B,H,S,hd]
// MODE 1: plain GEMM -> f32 C.
#define BM 128
#define BN 128
#define BKK 32
#define AROW 160                       // A bytes/row: 128 data + 32 pad
#define BROW 1088                      // B bytes/row: 1024 data + 64 pad
#define ATILE (BM * AROW)              // 20480
#define STAGEB (ATILE + 16 * BROW)     // 37888
#define GSTAGES 3
#define GEMM_SMEM (GSTAGES * STAGEB)   // 113664

template <int MODE>
__global__ __launch_bounds__(256, 2)
void gemm_kernel(const float2* __restrict__ A0, const float2* __restrict__ A1,
                 const float2* __restrict__ A2,
                 const float2* __restrict__ B0, const float2* __restrict__ B1,
                 const float2* __restrict__ B2,
                 __half* __restrict__ H0, __half* __restrict__ L0,
                 __half* __restrict__ H1, __half* __restrict__ L1,
                 __half* __restrict__ H2,
                 float* __restrict__ C)
{
    extern __shared__ char smraw[];
    const uint32_t smU = (uint32_t)__cvta_generic_to_shared(smraw);

    const int z = blockIdx.z;
    const float2* A = (z == 0) ? A0 : (z == 1) ? A1 : A2;
    const float2* B = (z == 0) ? B0 : (z == 1) ? B1 : B2;

    const int tid  = threadIdx.x;
    const int m0   = blockIdx.x * BM;
    const int n0   = blockIdx.y * BN;
    const int warp = tid >> 5;
    const int lane = tid & 31;
    const int warpM = warp & 1;          // 64-row halves
    const int warpN = warp >> 1;         // 32-col quarters
    const int g  = lane >> 2;
    const int tq = lane & 3;
    const int m0w = warpM * 64;
    const int n0w = warpN * 32;

    float acc[4][4][4];
#pragma unroll
    for (int i = 0; i < 4; i++)
#pragma unroll
        for (int j = 0; j < 4; j++)
#pragma unroll
            for (int r = 0; r < 4; r++) acc[i][j][r] = 0.f;

    auto load_tile = [&](int it, int s) {
        const int pc0 = it * 16;
        const uint32_t sb = smU + (uint32_t)s * STAGEB;
#pragma unroll
        for (int p = 0; p < 4; p++) {          // A: 1024 16B chunks
            int slot = tid + p * 256;
            int r = slot >> 3;
            int c = slot & 7;
            cp16s(sb + (uint32_t)(r * AROW + c * 16),
                  A + (size_t)(m0 + r) * (GK / 2) + pc0 + c * 2);
        }
#pragma unroll
        for (int p = 0; p < 4; p++) {          // B: 1024 16B chunks
            int slot = tid + p * 256;
            int r = slot >> 6;
            int c = slot & 63;
            cp16s(sb + (uint32_t)(ATILE + r * BROW + c * 16),
                  B + (size_t)(pc0 + r) * GN + n0 + c * 2);
        }
        asm volatile("cp.async.commit_group;");
    };

    const int NIT = GK / BKK;   // 32
    load_tile(0, 0);
    load_tile(1, 1);

    int sidx = 0;
    for (int it = 0; it < NIT; it++) {
        if (it + 1 < NIT) {
            asm volatile("cp.async.wait_group 1;");   // tile it landed
        } else {
            asm volatile("cp.async.wait_group 0;");
        }
        __syncthreads();   // tile it visible everywhere; compute(it-1) done

        if (it + 2 < NIT) {
            int sl = sidx + 2; if (sl >= GSTAGES) sl -= GSTAGES;
            load_tile(it + 2, sl);   // overwrites buffer compute(it-1) used
        }

        const char* sb = smraw + sidx * STAGEB;
#pragma unroll
        for (int ks = 0; ks < 4; ks++) {
            const int pr = 4 * ks + tq;        // pair-row index
            float2 bf[4];
#pragma unroll
            for (int nf = 0; nf < 4; nf++)
                bf[nf] = *(const float2*)(sb + ATILE + pr * BROW
                                          + (n0w + nf * 8 + g) * 8);
#pragma unroll
            for (int mf = 0; mf < 4; mf++) {
                const char* ar = sb + (m0w + mf * 16 + g) * AROW + pr * 8;
                float2 alo = *(const float2*)ar;
                float2 ahi = *(const float2*)(ar + 8 * AROW);
#pragma unroll
                for (int nf = 0; nf < 4; nf++) {
                    asm volatile(
                        "mma.sync.aligned.m16n8k8.row.col.f32.tf32.tf32.f32 "
                        "{%0,%1,%2,%3}, {%4,%5,%6,%7}, {%8,%9}, {%0,%1,%2,%3};"
                        : "+f"(acc[mf][nf][0]), "+f"(acc[mf][nf][1]),
                          "+f"(acc[mf][nf][2]), "+f"(acc[mf][nf][3])
                        : "r"(__float_as_uint(alo.x)), "r"(__float_as_uint(ahi.x)),
                          "r"(__float_as_uint(alo.y)), "r"(__float_as_uint(ahi.y)),
                          "r"(__float_as_uint(bf[nf].x)), "r"(__float_as_uint(bf[nf].y)));
                }
            }
        }
        sidx = sidx + 1; if (sidx >= GSTAGES) sidx -= GSTAGES;
    }

    // ---- epilogue
    const float scl = (MODE == 0 && z == 0) ? QSCALE : 1.f;
    __half* OH = (z == 0) ? H0 : (z == 1) ? H1 : H2;
    __half* OL = (z == 0) ? L0 : L1;                 // unused for z==2
#pragma unroll
    for (int mf = 0; mf < 4; mf++) {
#pragma unroll
        for (int nf = 0; nf < 4; nf++) {
            const int gcol = n0 + n0w + nf * 8 + 2 * tq;
#pragma unroll
            for (int half = 0; half < 2; half++) {
                const int grow = m0 + m0w + mf * 16 + g + half * 8;
                float x0 = acc[mf][nf][half * 2]     * scl;
                float x1 = acc[mf][nf][half * 2 + 1] * scl;
                if (MODE == 0) {
                    const int bb = grow >> 11, ss = grow & 2047;
                    const int hh = gcol >> 6, e = gcol & 63;
                    const size_t idx =
                        (((size_t)(bb * NHEAD + hh)) * SEQ + ss) * HDIM + e;
                    __half h0 = __float2half_rn(x0);
                    __half h1 = __float2half_rn(x1);
                    __half2 hv; hv.x = h0; hv.y = h1;
                    *(__half2*)(OH + idx) = hv;
                    if (z < 2) {
                        __half l0 = __float2half_rn(x0 - __half2float(h0));
                        __half l1 = __float2half_rn(x1 - __half2float(h1));
                        __half2 lv; lv.x = l0; lv.y = l1;
                        *(__half2*)(OL + idx) = lv;
                    }
                } else {
                    *(float2*)(C + (size_t)grow * GN + gcol) =
                        make_float2(x0, x1);
                }
            }
        }
    }
}

// ================= MMA flash attention (R11, unchanged) =====================
#define TQA 128
#define TKA 64

#define OFF_QHI 0
#define OFF_QLO 18432
#define OFF_STG 36864
#define STG_B   27648     // Khi 9216 + Klo 9216 + V 9216
#define OFF_QM  92160
#define OFF_KM  92672
#define ATTN_SMEM 93696

#define MMA16816(CC, A0, A1, A2, A3, B0, B1)                                  \
    asm volatile(                                                             \
        "mma.sync.aligned.m16n8k16.row.col.f32.f16.f16.f32 "                  \
        "{%0,%1,%2,%3}, {%4,%5,%6,%7}, {%8,%9}, {%0,%1,%2,%3};"               \
        : "+f"((CC)[0]), "+f"((CC)[1]), "+f"((CC)[2]), "+f"((CC)[3])          \
        : "r"(A0), "r"(A1), "r"(A2), "r"(A3), "r"(B0), "r"(B1))

#define LDSM_X4(R0, R1, R2, R3, ADDR)                                         \
    asm volatile("ldmatrix.sync.aligned.m8n8.x4.shared.b16 {%0,%1,%2,%3}, [%4];" \
                 : "=r"(R0), "=r"(R1), "=r"(R2), "=r"(R3) : "r"(ADDR))

#define LDSM_X4T(R0, R1, R2, R3, ADDR)                                        \
    asm volatile("ldmatrix.sync.aligned.m8n8.x4.trans.shared.b16 {%0,%1,%2,%3}, [%4];" \
                 : "=r"(R0), "=r"(R1), "=r"(R2), "=r"(R3) : "r"(ADDR))

__device__ __forceinline__ uint32_t pack_h2(float a, float b) {
    __half2 h = __floats2half2_rn(a, b);
    return *(uint32_t*)&h;
}

__global__ __launch_bounds__(256, 2)
void attn_mma_kernel(const __half* __restrict__ QHI, const __half* __restrict__ QLO,
                     const __half* __restrict__ KHI, const __half* __restrict__ KLO,
                     const __half* __restrict__ V16, const int* __restrict__ mask,
                     float2* __restrict__ AOP)
{
    extern __shared__ char smem_raw[];
    const uint32_t smU = (uint32_t)__cvta_generic_to_shared(smem_raw);

    const int b = blockIdx.z, h = blockIdx.y;
    const int qt = (int)gridDim.x - 1 - (int)blockIdx.x;   // heavy tiles first
    const int q0 = qt * TQA;
    const size_t base = ((size_t)(b * NHEAD + h)) * SEQ * HDIM;
    const int mrow = b * SEQ;

    const int tid  = threadIdx.x;
    const int warp = tid >> 5, lane = tid & 31;
    const int g = lane >> 2, t = lane & 3;

    auto load_tile = [&](int t0n, int s) {
        const uint32_t sb = smU + OFF_STG + (uint32_t)s * STG_B;
#pragma unroll
        for (int p = 0; p < 6; p++) {
            int slot = tid + p * 256;
            int arr  = slot >> 9;                // 0=Khi 1=Klo 2=V
            int rem  = slot & 511;
            int r    = rem >> 3;
            int cB   = (rem & 7) * 16;
            const __half* src = (arr == 0) ? KHI : (arr == 1) ? KLO : V16;
            cp16s(sb + (uint32_t)(arr * 9216 + r * 144 + cB),
                  src + base + (size_t)(t0n + r) * HDIM + (cB >> 1));
        }
        if (tid < 16)
            cp16s(smU + OFF_KM + (uint32_t)(s * 256 + tid * 16),
                  mask + mrow + t0n + tid * 4);
        asm volatile("cp.async.commit_group;");
    };

    {
#pragma unroll
        for (int p = 0; p < 8; p++) {
            int slot = tid + p * 256;
            int arr  = slot >> 10;               // 0=Qhi 1=Qlo
            int rem  = slot & 1023;
            int r    = rem >> 3;
            int cB   = (rem & 7) * 16;
            const __half* src = arr ? QLO : QHI;
            cp16s(smU + (arr ? OFF_QLO : OFF_QHI) + (uint32_t)(r * 144 + cB),
                  src + base + (size_t)(q0 + r) * HDIM + (cB >> 1));
        }
        if (tid < 32)
            cp16s(smU + OFF_QM + (uint32_t)(tid * 16), mask + mrow + q0 + tid * 4);
    }
    load_tile(0, 0);

    const int r0l = warp * 16 + g;
    const int r1l = r0l + 8;
    const int srow0 = q0 + r0l, srow1 = q0 + r1l;

    const float NEGINF = __int_as_float(0xff800000u);
    float m0 = NEGINF, m1 = NEGINF, l0 = 0.f, l1 = 0.f;
    float acc[8][4];
#pragma unroll
    for (int i = 0; i < 8; i++)
#pragma unroll
        for (int j = 0; j < 4; j++) acc[i][j] = 0.f;

    const uint32_t qoff = (uint32_t)((warp * 16 + (lane & 15)) * 144
                                     + (lane >> 4) * 16);
    const uint32_t koff = (uint32_t)((((lane >> 4) * 8) + (lane & 7)) * 144
                                     + ((lane >> 3) & 1) * 16);
    const uint32_t voff = (uint32_t)((lane & 15) * 144 + (lane >> 4) * 16);
    const uint32_t qhiB = smU + OFF_QHI + qoff;
    const uint32_t qloB = smU + OFF_QLO + qoff;

    const int* qm = (const int*)(smem_raw + OFF_QM);

    const int ntiles = (q0 + TQA) / TKA;
    for (int kt = 0; kt < ntiles; kt++) {
        const int t0 = kt * TKA;
        asm volatile("cp.async.wait_group 0;");
        __syncthreads();

        if (kt + 1 < ntiles) load_tile(t0 + TKA, (kt + 1) & 1);

        const uint32_t stb  = smU + OFF_STG + (uint32_t)(kt & 1) * STG_B;
        const uint32_t khiB = stb + koff;
        const uint32_t kloB = stb + 9216 + koff;
        const uint32_t vB   = stb + 18432 + voff;
        const int* km = (const int*)(smem_raw + OFF_KM + (kt & 1) * 256);

        float sc[8][4];
#pragma unroll
        for (int i = 0; i < 8; i++)
#pragma unroll
            for (int j = 0; j < 4; j++) sc[i][j] = 0.f;

#pragma unroll
        for (int kj = 0; kj < 4; kj++) {
            uint32_t ah0, ah1, ah2, ah3, al0, al1, al2, al3;
            LDSM_X4(ah0, ah1, ah2, ah3, qhiB + kj * 32);
            LDSM_X4(al0, al1, al2, al3, qloB + kj * 32);
#pragma unroll
            for (int nfp = 0; nfp < 4; nfp++) {
                const uint32_t kk = (uint32_t)(nfp * 16 * 144 + kj * 32);
                uint32_t bh0, bh1, bh2, bh3, bl0, bl1, bl2, bl3;
                LDSM_X4(bh0, bh1, bh2, bh3, khiB + kk);
                LDSM_X4(bl0, bl1, bl2, bl3, kloB + kk);
                MMA16816(sc[2 * nfp],     ah0, ah1, ah2, ah3, bh0, bh1);
                MMA16816(sc[2 * nfp],     ah0, ah1, ah2, ah3, bl0, bl1);
                MMA16816(sc[2 * nfp],     al0, al1, al2, al3, bh0, bh1);
                MMA16816(sc[2 * nfp + 1], ah0, ah1, ah2, ah3, bh2, bh3);
                MMA16816(sc[2 * nfp + 1], ah0, ah1, ah2, ah3, bl2, bl3);
                MMA16816(sc[2 * nfp + 1], al0, al1, al2, al3, bh2, bh3);
            }
        }

        const bool rm0 = (qm[r0l] != 0), rm1 = (qm[r1l] != 0);
        float mx0 = m0, mx1 = m1;
        if (t0 + TKA > q0) {
#pragma unroll
            for (int nf = 0; nf < 8; nf++) {
                const int c0i = nf * 8 + 2 * t, c1i = c0i + 1;
                const bool cm0 = (km[c0i] != 0), cm1 = (km[c1i] != 0);
                const int tc0 = t0 + c0i, tc1 = t0 + c1i;
                float v00 = (rm0 | cm0) ? 0.f : sc[nf][0]; if (tc0 > srow0) v00 = -1e30f;
                float v01 = (rm0 | cm1) ? 0.f : sc[nf][1]; if (tc1 > srow0) v01 = -1e30f;
                float v10 = (rm1 | cm0) ? 0.f : sc[nf][2]; if (tc0 > srow1) v10 = -1e30f;
                float v11 = (rm1 | cm1) ? 0.f : sc[nf][3]; if (tc1 > srow1) v11 = -1e30f;
                sc[nf][0] = v00; sc[nf][1] = v01; sc[nf][2] = v10; sc[nf][3] = v11;
                mx0 = fmaxf(mx0, fmaxf(v00, v01));
                mx1 = fmaxf(mx1, fmaxf(v10, v11));
            }
        } else {
#pragma unroll
            for (int nf = 0; nf < 8; nf++) {
                const int c0i = nf * 8 + 2 * t, c1i = c0i + 1;
                const bool cm0 = (km[c0i] != 0), cm1 = (km[c1i] != 0);
                float v00 = (rm0 | cm0) ? 0.f : sc[nf][0];
                float v01 = (rm0 | cm1) ? 0.f : sc[nf][1];
                float v10 = (rm1 | cm0) ? 0.f : sc[nf][2];
                float v11 = (rm1 | cm1) ? 0.f : sc[nf][3];
                sc[nf][0] = v00; sc[nf][1] = v01; sc[nf][2] = v10; sc[nf][3] = v11;
                mx0 = fmaxf(mx0, fmaxf(v00, v01));
                mx1 = fmaxf(mx1, fmaxf(v10, v11));
            }
        }
#pragma unroll
        for (int off = 1; off <= 2; off <<= 1) {
            mx0 = fmaxf(mx0, __shfl_xor_sync(0xffffffffu, mx0, off));
            mx1 = fmaxf(mx1, __shfl_xor_sync(0xffffffffu, mx1, off));
        }
        const float corr0 = ex2(m0 - mx0);
        const float corr1 = ex2(m1 - mx1);
        float rs0 = 0.f, rs1 = 0.f;
#pragma unroll
        for (int nf = 0; nf < 8; nf++) {
            float p00 = ex2(sc[nf][0] - mx0);
            float p01 = ex2(sc[nf][1] - mx0);
            float p10 = ex2(sc[nf][2] - mx1);
            float p11 = ex2(sc[nf][3] - mx1);
            sc[nf][0] = p00; sc[nf][1] = p01; sc[nf][2] = p10; sc[nf][3] = p11;
            rs0 += p00 + p01;
            rs1 += p10 + p11;
        }
#pragma unroll
        for (int off = 1; off <= 2; off <<= 1) {
            rs0 += __shfl_xor_sync(0xffffffffu, rs0, off);
            rs1 += __shfl_xor_sync(0xffffffffu, rs1, off);
        }
        l0 = l0 * corr0 + rs0;  m0 = mx0;
        l1 = l1 * corr1 + rs1;  m1 = mx1;
#pragma unroll
        for (int nfd = 0; nfd < 8; nfd++) {
            acc[nfd][0] *= corr0; acc[nfd][1] *= corr0;
            acc[nfd][2] *= corr1; acc[nfd][3] *= corr1;
        }

#pragma unroll
        for (int kj = 0; kj < 4; kj++) {
            uint32_t a0 = pack_h2(sc[2 * kj][0],     sc[2 * kj][1]);
            uint32_t a1 = pack_h2(sc[2 * kj][2],     sc[2 * kj][3]);
            uint32_t a2 = pack_h2(sc[2 * kj + 1][0], sc[2 * kj + 1][1]);
            uint32_t a3 = pack_h2(sc[2 * kj + 1][2], sc[2 * kj + 1][3]);
            const uint32_t vrow = vB + (uint32_t)(kj * 16 * 144);
#pragma unroll
            for (int p = 0; p < 4; p++) {
                uint32_t b0, b1, b2, b3;
                LDSM_X4T(b0, b1, b2, b3, vrow + (uint32_t)(p * 32));
                MMA16816(acc[2 * p],     a0, a1, a2, a3, b0, b1);
                MMA16816(acc[2 * p + 1], a0, a1, a2, a3, b2, b3);
            }
        }
    }

    // ---- epilogue: normalize + tf32-round, write pair layout for Wo GEMM
    const float inv0 = 1.f / l0, inv1 = 1.f / l1;
    float* AO = (float*)AOP;
#pragma unroll
    for (int nfd = 0; nfd < 8; nfd++) {
        const int pcb  = 4 * nfd + ((2 * t) & 3);
        const int comp = t >> 1;
        const size_t i00 = ((base + (size_t)srow0 * HDIM) + pcb * 2) + comp;
        const size_t i10 = ((base + (size_t)srow1 * HDIM) + pcb * 2) + comp;
        AO[i00]     = tfr(acc[nfd][0] * inv0);
        AO[i00 + 2] = tfr(acc[nfd][1] * inv0);
        AO[i10]     = tfr(acc[nfd][2] * inv1);
        AO[i10 + 2] = tfr(acc[nfd][3] * inv1);
    }
}

// ---------------- launch -----------------------------------------------------
extern "C" void kernel_launch(void* const* d_in, const int* in_sizes, int n_in,
                              void* d_out, int out_size)
{
    const float* q    = (const float*)d_in[0];
    const float* k    = (const float*)d_in[1];
    const float* v    = (const float*)d_in[2];
    const float* Wq   = (const float*)d_in[3];
    const float* Wk   = (const float*)d_in[4];
    const float* Wv   = (const float*)d_in[5];
    const float* Wo   = (const float*)d_in[6];
    const int*   mask = (const int*)d_in[7];
    float* out = (float*)d_out;

    float2 *apq, *apk, *apv, *aop, *bpq, *bpk, *bpv, *bpo;
    __half *q16h, *q16l, *k16h, *k16l, *v16;
    cudaGetSymbolAddress((void**)&apq, g_apq);
    cudaGetSymbolAddress((void**)&apk, g_apk);
    cudaGetSymbolAddress((void**)&apv, g_apv);
    cudaGetSymbolAddress((void**)&aop, g_aop);
    cudaGetSymbolAddress((void**)&bpq, g_bpq);
    cudaGetSymbolAddress((void**)&bpk, g_bpk);
    cudaGetSymbolAddress((void**)&bpv, g_bpv);
    cudaGetSymbolAddress((void**)&bpo, g_bpo);
    cudaGetSymbolAddress((void**)&q16h, g_q16h);
    cudaGetSymbolAddress((void**)&q16l, g_q16l);
    cudaGetSymbolAddress((void**)&k16h, g_k16h);
    cudaGetSymbolAddress((void**)&k16l, g_k16l);
    cudaGetSymbolAddress((void**)&v16,  g_v16);

    // combined preconvert: y 0..2 inputs (2048 blocks), y 3..6 weights (1024)
    dim3 gcv(2048, 7);
    cvt_all_kernel<<<gcv, 256>>>(q, k, v, Wq, Wk, Wv, Wo);

    cudaFuncSetAttribute(gemm_kernel<0>,
                         cudaFuncAttributeMaxDynamicSharedMemorySize, GEMM_SMEM);
    cudaFuncSetAttribute(gemm_kernel<1>,
                         cudaFuncAttributeMaxDynamicSharedMemorySize, GEMM_SMEM);

    // fused q/k/v projections -> fp16 hi/lo attention operands
    dim3 gp(GM / BM, GN / BN, 3);   // 32 x 8 x 3
    gemm_kernel<0><<<gp, 256, GEMM_SMEM>>>(apq, apk, apv, bpq, bpk, bpv,
                                           q16h, q16l, k16h, k16l, v16,
                                           nullptr);

    cudaFuncSetAttribute(attn_mma_kernel,
                         cudaFuncAttributeMaxDynamicSharedMemorySize, ATTN_SMEM);
    dim3 ga(SEQ / TQA, NHEAD, BATCH);   // 16 x 16 x 2
    attn_mma_kernel<<<ga, 256, ATTN_SMEM>>>(q16h, q16l, k16h, k16l, v16,
                                            mask, aop);

    // output projection: aop already tf32-rounded pair layout
    dim3 go(GM / BM, GN / BN, 1);   // 32 x 8
    gemm_kernel<1><<<go, 256, GEMM_SMEM>>>(aop, aop, aop, bpo, bpo, bpo,
                                           nullptr, nullptr, nullptr, nullptr,
                                           nullptr, out);
}